// round 15
// baseline (speedup 1.0000x reference)
#include <cuda_runtime.h>
#include <cuda_fp16.h>
#include <math.h>
#include <stdint.h>

#define B_  4
#define H_  8
#define N_  1024
#define DH_ 128
#define BH_ (B_*H_)
#define NTILES 8
#define SCALE_Q 0.08838834764831845f  /* 1/sqrt(128) */

// ---------------- smem layout (bytes) ----------------
#define OFF_QH   0
#define OFF_K0   32768
#define OFF_K1   65536
#define OFF_V0   98304
#define OFF_V1   131072
#define OFF_DK0  163840              /* float4[128] = 2048 */
#define OFF_DK1  165888
#define OFF_RS   167936              /* float[256] */
#define OFF_INV  168960              /* float[128] */
#define OFF_SC   169472              /* float      */
#define SMEM_TOTAL 169536
/* O-reduction scratch (64KB) reuses OFF_QH..OFF_K1 at the end */

// ---------------- global scratch ----------------
__device__ __half g_qh[256*16384];
__device__ __half g_kh[256*16384];
__device__ __half g_vh[256*16384];
__device__ __half g_p16[(size_t)BH_*N_*N_];   /* raw scores, fp16 */
__device__ float4 g_dk4[B_*N_];

// ---------------- helpers ----------------
__device__ __forceinline__ uint32_t smem_u32(const void* p){
    uint32_t a;
    asm("{ .reg .u64 t; cvta.to.shared.u64 t, %1; cvt.u32.u64 %0, t; }" : "=r"(a) : "l"(p));
    return a;
}
__device__ __forceinline__ void ldsm4(uint32_t* r, uint32_t addr){
    asm volatile("ldmatrix.sync.aligned.m8n8.x4.shared.b16 {%0,%1,%2,%3}, [%4];"
        : "=r"(r[0]), "=r"(r[1]), "=r"(r[2]), "=r"(r[3]) : "r"(addr));
}
__device__ __forceinline__ void ldsm4t(uint32_t* r, uint32_t addr){
    asm volatile("ldmatrix.sync.aligned.m8n8.x4.trans.shared.b16 {%0,%1,%2,%3}, [%4];"
        : "=r"(r[0]), "=r"(r[1]), "=r"(r[2]), "=r"(r[3]) : "r"(addr));
}
__device__ __forceinline__ void mma16816(float* c, const uint32_t* a, const uint32_t* b){
    asm volatile("mma.sync.aligned.m16n8k16.row.col.f32.f16.f16.f32 "
        "{%0,%1,%2,%3}, {%4,%5,%6,%7}, {%8,%9}, {%0,%1,%2,%3};"
        : "+f"(c[0]), "+f"(c[1]), "+f"(c[2]), "+f"(c[3])
        : "r"(a[0]), "r"(a[1]), "r"(a[2]), "r"(a[3]), "r"(b[0]), "r"(b[1]));
}
// swizzled byte offset in a 128x128 half tile
__device__ __forceinline__ int swzel(int row, int col){
    return ((col >> 6) << 14) + ((row >> 3) << 10) + ((row & 7) << 7)
         + ((((col & 63) << 1)) ^ ((row & 7) << 4));
}
__device__ __forceinline__ uint32_t h2u(__half2 x){ return *reinterpret_cast<uint32_t*>(&x); }
__device__ __forceinline__ __half2 pack2(float a, float b){
    return __float22half2_rn(make_float2(a, b));
}
// cp.async 16B
__device__ __forceinline__ void cpa16(uint32_t sdst, size_t gsrc){
    asm volatile("cp.async.cg.shared.global [%0], [%1], 16;" :: "r"(sdst), "l"(gsrc) : "memory");
}
#define CPA_COMMIT() asm volatile("cp.async.commit_group;" ::: "memory")
#define CPA_WAIT0()  asm volatile("cp.async.wait_group 0;" ::: "memory")

// copy one 32KB tile: 8 x 16B per thread
__device__ __forceinline__ void cp_tile32k(uint32_t sdst, const void* gsrc, int tid){
    size_t gs = __cvta_generic_to_global(gsrc);
    #pragma unroll
    for (int i = 0; i < 8; i++){
        int off = (i * 256 + tid) * 16;
        cpa16(sdst + off, gs + off);
    }
}

// ---------------- prep: fp32 -> swizzled fp16 tiles ----------------
__global__ void k_prep(const float* __restrict__ q, const float* __restrict__ k,
                       const float* __restrict__ v, const float* __restrict__ d_k)
{
    const int blk = blockIdx.x, tid = threadIdx.x;
    if (blk < 768){
        const int which = blk >> 8;           // 0=Q, 1=K, 2=V
        const int tile  = blk & 255;          // bh*8 + tt
        const int bh = tile >> 3, tt = tile & 7;
        const float* src = (which == 0 ? q : (which == 1 ? k : v))
                         + ((size_t)bh * N_ + tt * 128) * DH_;
        char* dh = (char*)((which == 0 ? g_qh : (which == 1 ? g_kh : g_vh))
                         + (size_t)tile * 16384);
        const float sc = (which == 0) ? SCALE_Q : 1.0f;
        #pragma unroll 4
        for (int it = 0; it < 16; it++){
            int idx = it * 256 + tid;
            int row = idx >> 5, c4 = (idx & 31) * 4;
            float4 a = *(const float4*)(src + (size_t)row * DH_ + c4);
            a.x *= sc; a.y *= sc; a.z *= sc; a.w *= sc;
            int off = swzel(row, c4);
            *(uint2*)(dh + off) = make_uint2(h2u(pack2(a.x, a.y)), h2u(pack2(a.z, a.w)));
        }
    } else {
        int i = (blk - 768) * 256 + tid;      // 0 .. B_*N_-1
        float4 dv = *(const float4*)(d_k + (size_t)i * 4);
        g_dk4[i] = make_float4(dv.x, dv.y, dv.z, dv.x*dv.x + dv.y*dv.y + dv.z*dv.z);
    }
}

// ---------------- main tensor-core kernel ----------------
extern __shared__ __align__(16) char smem[];

__global__ __launch_bounds__(256)
void k_main(const float* __restrict__ c, const float* __restrict__ d_q,
            const float* __restrict__ w_w, const float* __restrict__ b_w,
            const float* __restrict__ w_b, const float* __restrict__ b_b,
            float* __restrict__ out, float* __restrict__ scores)
{
    const int tid  = threadIdx.x;
    const int w    = tid >> 5, lane = tid & 31;
    const int g    = lane >> 2, t = lane & 3;
    const int bh   = blockIdx.x >> 3, rt = blockIdx.x & 7;
    const int b    = bh >> 3, h = bh & 7;
    const int n0   = rt * 128;
    const int wm32 = (w & 3) * 32;
    const int wn   = w >> 2;
    const int nb64 = wn * 64;

    const uint32_t sb  = smem_u32(smem);
    const uint32_t sQH = sb + OFF_QH;
    const uint32_t sK[2] = { sb + OFF_K0, sb + OFF_K1 };
    const uint32_t sV[2] = { sb + OFF_V0, sb + OFF_V1 };

    __half* scbase = g_p16 + ((size_t)bh * N_ + n0) * (size_t)N_;

    // ---- prologue: issue cp.async for Q and tile 0, then softplus(c) sum ----
    cp_tile32k(sQH, g_qh + (size_t)blockIdx.x * 16384, tid);
    cp_tile32k(sK[0], g_kh + (size_t)(bh * 8 + 0) * 16384, tid);
    cp_tile32k(sV[0], g_vh + (size_t)(bh * 8 + 0) * 16384, tid);
    if (tid < 128)
        cpa16(sb + OFF_DK0 + tid * 16,
              __cvta_generic_to_global(g_dk4 + (size_t)b * N_) + tid * 16);
    CPA_COMMIT();

    // softplus(c) sum for this bh (overlaps the async copies)
    {
        const float* cp = c + (size_t)bh * N_;
        float s = 0.0f;
        #pragma unroll
        for (int i = 0; i < 4; i++){
            float x = cp[tid + i * 256];
            s += fmaxf(x, 0.0f) + log1pf(__expf(-fabsf(x)));
        }
        #pragma unroll
        for (int o = 16; o; o >>= 1) s += __shfl_xor_sync(0xffffffffu, s, o);
        if (lane == 0) ((float*)(smem + OFF_RS))[w] = s;
    }

    // ---- per-lane row constants ----
    const float ww = w_w[h], bw = b_w[h], wb = w_b[h], bb = b_b[h];
    const float m2w = -2.0f * ww, m2b = -2.0f * wb;
    float dqx_[2][2], dqy_[2][2], dqz_[2][2], aq_[2][2], ab_[2][2];
    #pragma unroll
    for (int fm = 0; fm < 2; fm++)
        #pragma unroll
        for (int rh = 0; rh < 2; rh++){
            int r = wm32 + fm * 16 + rh * 8 + g;
            float4 dv = *(const float4*)(d_q + ((size_t)b * N_ + n0 + r) * 4);
            dqx_[fm][rh] = dv.x; dqy_[fm][rh] = dv.y; dqz_[fm][rh] = dv.z;
            float sq = dv.x*dv.x + dv.y*dv.y + dv.z*dv.z;
            aq_[fm][rh] = fmaf(ww, sq, bw);
            ab_[fm][rh] = fmaf(wb, sq, bb);
        }

    float o_acc[2][16][4];
    #pragma unroll
    for (int fm = 0; fm < 2; fm++)
        #pragma unroll
        for (int fn = 0; fn < 16; fn++)
            #pragma unroll
            for (int e = 0; e < 4; e++) o_acc[fm][fn][e] = 0.0f;
    float rs_[2][2] = {{0.0f,0.0f},{0.0f,0.0f}};

    const int aRowOff = (lane & 15), aColOff = ((lane >> 4) << 3);
    const int bRowOff = (lane & 7) + (((lane >> 3) & 1) << 3), bColOff = ((lane >> 4) << 3);
    const int vtRow = (((lane >> 4) & 1) << 3) + (lane & 7), vtCol = (((lane >> 3) & 1) << 3);

    CPA_WAIT0();
    __syncthreads();
    if (tid == 0){
        const float* red = (const float*)(smem + OFF_RS);
        float ss = 0.0f;
        #pragma unroll
        for (int i = 0; i < 8; i++) ss += red[i];
        *(float*)(smem + OFF_SC) = ss;
    }
    __syncthreads();

    for (int mt = 0; mt < NTILES; mt++){
        const int m0 = mt * 128;
        const int cur = mt & 1;

        // ---- prefetch next tile into the other buffer ----
        if (mt + 1 < NTILES){
            cp_tile32k(sK[1 - cur], g_kh + (size_t)(bh * 8 + mt + 1) * 16384, tid);
            cp_tile32k(sV[1 - cur], g_vh + (size_t)(bh * 8 + mt + 1) * 16384, tid);
            if (tid < 128)
                cpa16(sb + (cur ? OFF_DK0 : OFF_DK1) + tid * 16,
                      __cvta_generic_to_global(g_dk4 + (size_t)b * N_ + (mt + 1) * 128) + tid * 16);
            CPA_COMMIT();
        }

        const uint32_t sKH = sK[cur], sVH = sV[cur];

        // ---- S = Qh Kh^T : single-pass fp16 ----
        float s_acc[2][8][4];
        #pragma unroll
        for (int fm = 0; fm < 2; fm++)
            #pragma unroll
            for (int fn = 0; fn < 8; fn++)
                #pragma unroll
                for (int e = 0; e < 4; e++) s_acc[fm][fn][e] = 0.0f;

        #pragma unroll
        for (int ks = 0; ks < 8; ks++){
            const int kc = ks * 16;
            uint32_t aqh0[4], aqh1[4];
            ldsm4(aqh0, sQH + swzel(wm32 +      aRowOff, kc + aColOff));
            ldsm4(aqh1, sQH + swzel(wm32 + 16 + aRowOff, kc + aColOff));
            #pragma unroll
            for (int blk = 0; blk < 4; blk++){
                uint32_t bkh[4];
                ldsm4(bkh, sKH + swzel(nb64 + blk * 16 + bRowOff, kc + bColOff));
                #pragma unroll
                for (int sub = 0; sub < 2; sub++){
                    uint32_t b2[2] = { bkh[sub], bkh[2 + sub] };
                    mma16816(s_acc[0][blk*2+sub], aqh0, b2);
                    mma16816(s_acc[1][blk*2+sub], aqh1, b2);
                }
            }
        }

        // ---- map epilogue: dist map + relu, rowsum, P -> fp16 (regs + gmem) ----
        uint32_t pah[2][4][4];
        const float4* dk4s = (const float4*)(smem + (cur ? OFF_DK1 : OFF_DK0));
        #pragma unroll
        for (int fn = 0; fn < 8; fn++){
            const int c0 = nb64 + fn * 8 + t * 2;
            const float4 dA = dk4s[c0];
            const float4 dB = dk4s[c0 + 1];
            const int kb = fn >> 1, base = (fn & 1) * 2;
            #pragma unroll
            for (int fm = 0; fm < 2; fm++){
                float p[4];
                #pragma unroll
                for (int e = 0; e < 4; e++){
                    const int rh = e >> 1;
                    const float4 dk = (e & 1) ? dB : dA;
                    float t3 = fmaf(dqx_[fm][rh], dk.x,
                               fmaf(dqy_[fm][rh], dk.y, dqz_[fm][rh] * dk.z));
                    float yw = fmaf(m2w, t3, fmaf(ww, dk.w, aq_[fm][rh]));
                    float db = fmaf(m2b, t3, fmaf(wb, dk.w, ab_[fm][rh]));
                    float z  = fmaxf(fabsf(yw) * -1.4426950408889634f, -126.0f);
                    float ex; asm("ex2.approx.f32 %0, %1;" : "=f"(ex) : "f"(z));
                    float lg; asm("lg2.approx.f32 %0, %1;" : "=f"(lg) : "f"(1.0f + ex));
                    float sp = fmaf(0.6931471805599453f, lg, fmaxf(-yw, 0.0f));
                    float pv = fmaf(s_acc[fm][fn][e], sp, db);
                    pv = fmaxf(pv, 0.0f);
                    p[e] = pv;
                    rs_[fm][rh] += pv;
                }
                uint32_t h01 = h2u(pack2(p[0], p[1]));
                uint32_t h23 = h2u(pack2(p[2], p[3]));
                pah[fm][kb][base + 0] = h01;
                pah[fm][kb][base + 1] = h23;
                const int r0 = wm32 + fm * 16 + g, r1 = r0 + 8;
                *(uint32_t*)(scbase + (size_t)r0 * N_ + m0 + c0) = h01;
                *(uint32_t*)(scbase + (size_t)r1 * N_ + m0 + c0) = h23;
            }
        }

        // ---- O += Ph Vh : single pass (A from registers) ----
        #pragma unroll
        for (int ks = 0; ks < 4; ks++){
            const int krow = nb64 + ks * 16;
            #pragma unroll
            for (int blk = 0; blk < 8; blk++){
                uint32_t bvh[4];
                ldsm4t(bvh, sVH + swzel(krow + vtRow, blk * 16 + vtCol));
                #pragma unroll
                for (int sub = 0; sub < 2; sub++){
                    uint32_t b2[2] = { bvh[sub], bvh[2 + sub] };
                    mma16816(o_acc[0][blk*2+sub], pah[0][ks], b2);
                    mma16816(o_acc[1][blk*2+sub], pah[1][ks], b2);
                }
            }
        }

        CPA_WAIT0();
        __syncthreads();
    }

    // ---- rowsum reduce; wn=1 stages O partial into (dead) Q/K smem ----
    float* RS = (float*)(smem + OFF_RS);
    #pragma unroll
    for (int fm = 0; fm < 2; fm++)
        #pragma unroll
        for (int rh = 0; rh < 2; rh++){
            float vsum = rs_[fm][rh];
            vsum += __shfl_xor_sync(0xffffffffu, vsum, 1);
            vsum += __shfl_xor_sync(0xffffffffu, vsum, 2);
            if (t == 0) RS[wn * 128 + wm32 + fm * 16 + rh * 8 + g] = vsum;
        }
    float* OS = (float*)(smem + OFF_QH);   // 64KB scratch: [row][d]
    if (wn == 1){
        #pragma unroll
        for (int fm = 0; fm < 2; fm++){
            const int r0 = wm32 + fm * 16 + g, r1 = r0 + 8;
            #pragma unroll
            for (int fn = 0; fn < 16; fn++){
                const int d0 = fn * 8 + t * 2;
                *(float2*)(OS + r0 * 128 + d0) = make_float2(o_acc[fm][fn][0], o_acc[fm][fn][1]);
                *(float2*)(OS + r1 * 128 + d0) = make_float2(o_acc[fm][fn][2], o_acc[fm][fn][3]);
            }
        }
    }
    __syncthreads();
    if (tid < 128){
        float detr = RS[tid] + RS[128 + tid] + *(const float*)(smem + OFF_SC) + 1e-9f;
        ((float*)(smem + OFF_INV))[tid] = 1.0f / detr;
    }
    __syncthreads();

    const float* INV = (const float*)(smem + OFF_INV);

    // ---- wn=0 combines halves, normalizes, writes O ----
    if (wn == 0){
        #pragma unroll
        for (int fm = 0; fm < 2; fm++){
            const int r0 = wm32 + fm * 16 + g, r1 = r0 + 8;
            const float i0 = INV[r0], i1 = INV[r1];
            float* ob0 = out + ((size_t)bh * N_ + n0 + r0) * DH_;
            float* ob1 = out + ((size_t)bh * N_ + n0 + r1) * DH_;
            #pragma unroll
            for (int fn = 0; fn < 16; fn++){
                const int d0 = fn * 8 + t * 2;
                float2 p0 = *(const float2*)(OS + r0 * 128 + d0);
                float2 p1 = *(const float2*)(OS + r1 * 128 + d0);
                *(float2*)(ob0 + d0) = make_float2((o_acc[fm][fn][0] + p0.x) * i0,
                                                   (o_acc[fm][fn][1] + p0.y) * i0);
                *(float2*)(ob1 + d0) = make_float2((o_acc[fm][fn][2] + p1.x) * i1,
                                                   (o_acc[fm][fn][3] + p1.y) * i1);
            }
        }
    }

    // ---- fused score normalization: this CTA's 128x1024 block (L2-hot) ----
    {
        float* dstp = scores + ((size_t)bh * N_ + n0) * (size_t)N_;
        const uint4* srcp = (const uint4*)scbase;   // 8 halves per unit
        #pragma unroll 4
        for (int u = tid; u < 16384; u += 256){
            const int row = u >> 7;                 // 128 units per row
            const float invd = INV[row];
            uint4 hv = srcp[u];
            float2 f0 = __half22float2(*(const __half2*)&hv.x);
            float2 f1 = __half22float2(*(const __half2*)&hv.y);
            float2 f2 = __half22float2(*(const __half2*)&hv.z);
            float2 f3 = __half22float2(*(const __half2*)&hv.w);
            *(float4*)(dstp + (size_t)u * 8)     = make_float4(f0.x * invd, f0.y * invd,
                                                               f1.x * invd, f1.y * invd);
            *(float4*)(dstp + (size_t)u * 8 + 4) = make_float4(f2.x * invd, f2.y * invd,
                                                               f3.x * invd, f3.y * invd);
        }
    }
}

extern "C" void kernel_launch(void* const* d_in, const int* in_sizes, int n_in,
                              void* d_out, int out_size)
{
    const float* q  = (const float*)d_in[0];
    const float* k  = (const float*)d_in[1];
    const float* v  = (const float*)d_in[2];
    const float* c  = (const float*)d_in[3];
    const float* dq = (const float*)d_in[4];
    const float* dk = (const float*)d_in[5];
    const float* ww = (const float*)d_in[6];
    const float* bw = (const float*)d_in[7];
    const float* wb = (const float*)d_in[8];
    const float* bb = (const float*)d_in[9];

    float* out    = (float*)d_out;
    float* scores = out + (size_t)BH_ * N_ * DH_;

    cudaFuncSetAttribute(k_main, cudaFuncAttributeMaxDynamicSharedMemorySize, SMEM_TOTAL);

    k_prep<<<784, 256>>>(q, k, v, dk);
    k_main<<<BH_ * 8, 256, SMEM_TOTAL>>>(c, dq, ww, bw, wb, bb, out, scores);
}

// round 16
// speedup vs baseline: 1.1839x; 1.1839x over previous
#include <cuda_runtime.h>
#include <cuda_fp16.h>
#include <math.h>
#include <stdint.h>

#define B_  4
#define H_  8
#define N_  1024
#define DH_ 128
#define BH_ (B_*H_)
#define NTILES 8
#define SCALE_Q 0.08838834764831845f  /* 1/sqrt(128) */

// ---------------- smem layout (bytes) ----------------
#define OFF_QH   0
#define OFF_K0   32768
#define OFF_K1   65536
#define OFF_V0   98304
#define OFF_V1   131072
#define OFF_DK0  163840              /* float4[128] = 2048 */
#define OFF_DK1  165888
#define OFF_RS   167936              /* float[256] */
#define OFF_INV  168960              /* float[128] */
#define OFF_SC   169472              /* float      */
#define SMEM_TOTAL 169536
/* O-reduction scratch (64KB) reuses OFF_QH..OFF_K1 at the end */

// ---------------- global scratch ----------------
__device__ __half g_qh[256*16384];
__device__ __half g_kh[256*16384];
__device__ __half g_vh[256*16384];
__device__ __half g_p16[(size_t)BH_*N_*N_];   /* raw scores, fp16 */
__device__ float4 g_dk4[B_*N_];
__device__ float  g_inv[BH_*N_];

// ---------------- helpers ----------------
__device__ __forceinline__ uint32_t smem_u32(const void* p){
    uint32_t a;
    asm("{ .reg .u64 t; cvta.to.shared.u64 t, %1; cvt.u32.u64 %0, t; }" : "=r"(a) : "l"(p));
    return a;
}
__device__ __forceinline__ void ldsm4(uint32_t* r, uint32_t addr){
    asm volatile("ldmatrix.sync.aligned.m8n8.x4.shared.b16 {%0,%1,%2,%3}, [%4];"
        : "=r"(r[0]), "=r"(r[1]), "=r"(r[2]), "=r"(r[3]) : "r"(addr));
}
__device__ __forceinline__ void ldsm4t(uint32_t* r, uint32_t addr){
    asm volatile("ldmatrix.sync.aligned.m8n8.x4.trans.shared.b16 {%0,%1,%2,%3}, [%4];"
        : "=r"(r[0]), "=r"(r[1]), "=r"(r[2]), "=r"(r[3]) : "r"(addr));
}
__device__ __forceinline__ void mma16816(float* c, const uint32_t* a, const uint32_t* b){
    asm volatile("mma.sync.aligned.m16n8k16.row.col.f32.f16.f16.f32 "
        "{%0,%1,%2,%3}, {%4,%5,%6,%7}, {%8,%9}, {%0,%1,%2,%3};"
        : "+f"(c[0]), "+f"(c[1]), "+f"(c[2]), "+f"(c[3])
        : "r"(a[0]), "r"(a[1]), "r"(a[2]), "r"(a[3]), "r"(b[0]), "r"(b[1]));
}
// swizzled byte offset in a 128x128 half tile
__device__ __forceinline__ int swzel(int row, int col){
    return ((col >> 6) << 14) + ((row >> 3) << 10) + ((row & 7) << 7)
         + ((((col & 63) << 1)) ^ ((row & 7) << 4));
}
__device__ __forceinline__ uint32_t h2u(__half2 x){ return *reinterpret_cast<uint32_t*>(&x); }
__device__ __forceinline__ __half2 pack2(float a, float b){
    return __float22half2_rn(make_float2(a, b));
}
// cp.async 16B
__device__ __forceinline__ void cpa16(uint32_t sdst, size_t gsrc){
    asm volatile("cp.async.cg.shared.global [%0], [%1], 16;" :: "r"(sdst), "l"(gsrc) : "memory");
}
#define CPA_COMMIT() asm volatile("cp.async.commit_group;" ::: "memory")
#define CPA_WAIT0()  asm volatile("cp.async.wait_group 0;" ::: "memory")

// copy one 32KB tile: 8 x 16B per thread
__device__ __forceinline__ void cp_tile32k(uint32_t sdst, const void* gsrc, int tid){
    size_t gs = __cvta_generic_to_global(gsrc);
    #pragma unroll
    for (int i = 0; i < 8; i++){
        int off = (i * 256 + tid) * 16;
        cpa16(sdst + off, gs + off);
    }
}

// ---------------- prep: fp32 -> swizzled fp16 tiles ----------------
__global__ void k_prep(const float* __restrict__ q, const float* __restrict__ k,
                       const float* __restrict__ v, const float* __restrict__ d_k)
{
    const int blk = blockIdx.x, tid = threadIdx.x;
    if (blk < 768){
        const int which = blk >> 8;           // 0=Q, 1=K, 2=V
        const int tile  = blk & 255;          // bh*8 + tt
        const int bh = tile >> 3, tt = tile & 7;
        const float* src = (which == 0 ? q : (which == 1 ? k : v))
                         + ((size_t)bh * N_ + tt * 128) * DH_;
        char* dh = (char*)((which == 0 ? g_qh : (which == 1 ? g_kh : g_vh))
                         + (size_t)tile * 16384);
        const float sc = (which == 0) ? SCALE_Q : 1.0f;
        #pragma unroll 4
        for (int it = 0; it < 16; it++){
            int idx = it * 256 + tid;
            int row = idx >> 5, c4 = (idx & 31) * 4;
            float4 a = *(const float4*)(src + (size_t)row * DH_ + c4);
            a.x *= sc; a.y *= sc; a.z *= sc; a.w *= sc;
            int off = swzel(row, c4);
            *(uint2*)(dh + off) = make_uint2(h2u(pack2(a.x, a.y)), h2u(pack2(a.z, a.w)));
        }
    } else {
        int i = (blk - 768) * 256 + tid;      // 0 .. B_*N_-1
        float4 dv = *(const float4*)(d_k + (size_t)i * 4);
        g_dk4[i] = make_float4(dv.x, dv.y, dv.z, dv.x*dv.x + dv.y*dv.y + dv.z*dv.z);
    }
}

// ---------------- main tensor-core kernel ----------------
extern __shared__ __align__(16) char smem[];

__global__ __launch_bounds__(256)
void k_main(const float* __restrict__ c, const float* __restrict__ d_q,
            const float* __restrict__ w_w, const float* __restrict__ b_w,
            const float* __restrict__ w_b, const float* __restrict__ b_b,
            float* __restrict__ out)
{
    const int tid  = threadIdx.x;
    const int w    = tid >> 5, lane = tid & 31;
    const int g    = lane >> 2, t = lane & 3;
    const int bh   = blockIdx.x >> 3, rt = blockIdx.x & 7;
    const int b    = bh >> 3, h = bh & 7;
    const int n0   = rt * 128;
    const int wm32 = (w & 3) * 32;
    const int wn   = w >> 2;
    const int nb64 = wn * 64;

    const uint32_t sb  = smem_u32(smem);
    const uint32_t sQH = sb + OFF_QH;
    const uint32_t sK[2] = { sb + OFF_K0, sb + OFF_K1 };
    const uint32_t sV[2] = { sb + OFF_V0, sb + OFF_V1 };

    __half* scbase = g_p16 + ((size_t)bh * N_ + n0) * (size_t)N_;

    // ---- prologue: issue cp.async for Q and tile 0, then softplus(c) sum ----
    cp_tile32k(sQH, g_qh + (size_t)blockIdx.x * 16384, tid);
    cp_tile32k(sK[0], g_kh + (size_t)(bh * 8 + 0) * 16384, tid);
    cp_tile32k(sV[0], g_vh + (size_t)(bh * 8 + 0) * 16384, tid);
    if (tid < 128)
        cpa16(sb + OFF_DK0 + tid * 16,
              __cvta_generic_to_global(g_dk4 + (size_t)b * N_) + tid * 16);
    CPA_COMMIT();

    // softplus(c) sum for this bh (overlaps the async copies)
    {
        const float* cp = c + (size_t)bh * N_;
        float s = 0.0f;
        #pragma unroll
        for (int i = 0; i < 4; i++){
            float x = cp[tid + i * 256];
            s += fmaxf(x, 0.0f) + log1pf(__expf(-fabsf(x)));
        }
        #pragma unroll
        for (int o = 16; o; o >>= 1) s += __shfl_xor_sync(0xffffffffu, s, o);
        if (lane == 0) ((float*)(smem + OFF_RS))[w] = s;
    }

    // ---- per-lane row constants ----
    const float ww = w_w[h], bw = b_w[h], wb = w_b[h], bb = b_b[h];
    const float m2w = -2.0f * ww, m2b = -2.0f * wb;
    float dqx_[2][2], dqy_[2][2], dqz_[2][2], aq_[2][2], ab_[2][2];
    #pragma unroll
    for (int fm = 0; fm < 2; fm++)
        #pragma unroll
        for (int rh = 0; rh < 2; rh++){
            int r = wm32 + fm * 16 + rh * 8 + g;
            float4 dv = *(const float4*)(d_q + ((size_t)b * N_ + n0 + r) * 4);
            dqx_[fm][rh] = dv.x; dqy_[fm][rh] = dv.y; dqz_[fm][rh] = dv.z;
            float sq = dv.x*dv.x + dv.y*dv.y + dv.z*dv.z;
            aq_[fm][rh] = fmaf(ww, sq, bw);
            ab_[fm][rh] = fmaf(wb, sq, bb);
        }

    float o_acc[2][16][4];
    #pragma unroll
    for (int fm = 0; fm < 2; fm++)
        #pragma unroll
        for (int fn = 0; fn < 16; fn++)
            #pragma unroll
            for (int e = 0; e < 4; e++) o_acc[fm][fn][e] = 0.0f;
    float rs_[2][2] = {{0.0f,0.0f},{0.0f,0.0f}};

    const int aRowOff = (lane & 15), aColOff = ((lane >> 4) << 3);
    const int bRowOff = (lane & 7) + (((lane >> 3) & 1) << 3), bColOff = ((lane >> 4) << 3);
    const int vtRow = (((lane >> 4) & 1) << 3) + (lane & 7), vtCol = (((lane >> 3) & 1) << 3);

    CPA_WAIT0();
    __syncthreads();
    if (tid == 0){
        const float* red = (const float*)(smem + OFF_RS);
        float ss = 0.0f;
        #pragma unroll
        for (int i = 0; i < 8; i++) ss += red[i];
        *(float*)(smem + OFF_SC) = ss;
    }
    __syncthreads();

    for (int mt = 0; mt < NTILES; mt++){
        const int m0 = mt * 128;
        const int cur = mt & 1;

        // ---- prefetch next tile into the other buffer ----
        if (mt + 1 < NTILES){
            cp_tile32k(sK[1 - cur], g_kh + (size_t)(bh * 8 + mt + 1) * 16384, tid);
            cp_tile32k(sV[1 - cur], g_vh + (size_t)(bh * 8 + mt + 1) * 16384, tid);
            if (tid < 128)
                cpa16(sb + (cur ? OFF_DK0 : OFF_DK1) + tid * 16,
                      __cvta_generic_to_global(g_dk4 + (size_t)b * N_ + (mt + 1) * 128) + tid * 16);
            CPA_COMMIT();
        }

        const uint32_t sKH = sK[cur], sVH = sV[cur];

        // ---- S = Qh Kh^T : single-pass fp16 ----
        float s_acc[2][8][4];
        #pragma unroll
        for (int fm = 0; fm < 2; fm++)
            #pragma unroll
            for (int fn = 0; fn < 8; fn++)
                #pragma unroll
                for (int e = 0; e < 4; e++) s_acc[fm][fn][e] = 0.0f;

        #pragma unroll
        for (int ks = 0; ks < 8; ks++){
            const int kc = ks * 16;
            uint32_t aqh0[4], aqh1[4];
            ldsm4(aqh0, sQH + swzel(wm32 +      aRowOff, kc + aColOff));
            ldsm4(aqh1, sQH + swzel(wm32 + 16 + aRowOff, kc + aColOff));
            #pragma unroll
            for (int blk = 0; blk < 4; blk++){
                uint32_t bkh[4];
                ldsm4(bkh, sKH + swzel(nb64 + blk * 16 + bRowOff, kc + bColOff));
                #pragma unroll
                for (int sub = 0; sub < 2; sub++){
                    uint32_t b2[2] = { bkh[sub], bkh[2 + sub] };
                    mma16816(s_acc[0][blk*2+sub], aqh0, b2);
                    mma16816(s_acc[1][blk*2+sub], aqh1, b2);
                }
            }
        }

        // ---- interleaved: per kb slab, epilogue (2 fn) then PV MMAs for that slab ----
        const float4* dk4s = (const float4*)(smem + (cur ? OFF_DK1 : OFF_DK0));
        #pragma unroll
        for (int kb = 0; kb < 4; kb++){
            uint32_t pah[2][4];
            // epilogue for fn = 2*kb, 2*kb+1
            #pragma unroll
            for (int fi = 0; fi < 2; fi++){
                const int fn = kb * 2 + fi;
                const int c0 = nb64 + fn * 8 + t * 2;
                const float4 dA = dk4s[c0];
                const float4 dB = dk4s[c0 + 1];
                #pragma unroll
                for (int fm = 0; fm < 2; fm++){
                    float p[4];
                    #pragma unroll
                    for (int e = 0; e < 4; e++){
                        const int rh = e >> 1;
                        const float4 dk = (e & 1) ? dB : dA;
                        float t3 = fmaf(dqx_[fm][rh], dk.x,
                                   fmaf(dqy_[fm][rh], dk.y, dqz_[fm][rh] * dk.z));
                        float yw = fmaf(m2w, t3, fmaf(ww, dk.w, aq_[fm][rh]));
                        float db = fmaf(m2b, t3, fmaf(wb, dk.w, ab_[fm][rh]));
                        float z  = fmaxf(fabsf(yw) * -1.4426950408889634f, -126.0f);
                        float ex; asm("ex2.approx.f32 %0, %1;" : "=f"(ex) : "f"(z));
                        float lg; asm("lg2.approx.f32 %0, %1;" : "=f"(lg) : "f"(1.0f + ex));
                        float sp = fmaf(0.6931471805599453f, lg, fmaxf(-yw, 0.0f));
                        float pv = fmaf(s_acc[fm][fn][e], sp, db);
                        pv = fmaxf(pv, 0.0f);
                        p[e] = pv;
                        rs_[fm][rh] += pv;
                    }
                    uint32_t h01 = h2u(pack2(p[0], p[1]));
                    uint32_t h23 = h2u(pack2(p[2], p[3]));
                    pah[fm][fi * 2 + 0] = h01;
                    pah[fm][fi * 2 + 1] = h23;
                    const int r0 = wm32 + fm * 16 + g, r1 = r0 + 8;
                    *(uint32_t*)(scbase + (size_t)r0 * N_ + m0 + c0) = h01;
                    *(uint32_t*)(scbase + (size_t)r1 * N_ + m0 + c0) = h23;
                }
            }
            // PV for this k-slab (krow = nb64 + kb*16)
            const int krow = nb64 + kb * 16;
            #pragma unroll
            for (int blk = 0; blk < 8; blk++){
                uint32_t bvh[4];
                ldsm4t(bvh, sVH + swzel(krow + vtRow, blk * 16 + vtCol));
                #pragma unroll
                for (int sub = 0; sub < 2; sub++){
                    uint32_t b2[2] = { bvh[sub], bvh[2 + sub] };
                    mma16816(o_acc[0][blk*2+sub], pah[0], b2);
                    mma16816(o_acc[1][blk*2+sub], pah[1], b2);
                }
            }
        }

        CPA_WAIT0();
        __syncthreads();
    }

    // ---- rowsum reduce; wn=1 stages O partial into (dead) Q/K smem ----
    float* RS = (float*)(smem + OFF_RS);
    #pragma unroll
    for (int fm = 0; fm < 2; fm++)
        #pragma unroll
        for (int rh = 0; rh < 2; rh++){
            float vsum = rs_[fm][rh];
            vsum += __shfl_xor_sync(0xffffffffu, vsum, 1);
            vsum += __shfl_xor_sync(0xffffffffu, vsum, 2);
            if (t == 0) RS[wn * 128 + wm32 + fm * 16 + rh * 8 + g] = vsum;
        }
    float* OS = (float*)(smem + OFF_QH);   // 64KB scratch: [row][d]
    if (wn == 1){
        #pragma unroll
        for (int fm = 0; fm < 2; fm++){
            const int r0 = wm32 + fm * 16 + g, r1 = r0 + 8;
            #pragma unroll
            for (int fn = 0; fn < 16; fn++){
                const int d0 = fn * 8 + t * 2;
                *(float2*)(OS + r0 * 128 + d0) = make_float2(o_acc[fm][fn][0], o_acc[fm][fn][1]);
                *(float2*)(OS + r1 * 128 + d0) = make_float2(o_acc[fm][fn][2], o_acc[fm][fn][3]);
            }
        }
    }
    __syncthreads();
    if (tid < 128){
        float detr = RS[tid] + RS[128 + tid] + *(const float*)(smem + OFF_SC) + 1e-9f;
        float inv = 1.0f / detr;
        ((float*)(smem + OFF_INV))[tid] = inv;
        g_inv[(size_t)bh * N_ + n0 + tid] = inv;
    }
    __syncthreads();

    // ---- wn=0 combines halves, normalizes, writes O ----
    if (wn == 0){
        const float* INV = (const float*)(smem + OFF_INV);
        #pragma unroll
        for (int fm = 0; fm < 2; fm++){
            const int r0 = wm32 + fm * 16 + g, r1 = r0 + 8;
            const float i0 = INV[r0], i1 = INV[r1];
            float* ob0 = out + ((size_t)bh * N_ + n0 + r0) * DH_;
            float* ob1 = out + ((size_t)bh * N_ + n0 + r1) * DH_;
            #pragma unroll
            for (int fn = 0; fn < 16; fn++){
                const int d0 = fn * 8 + t * 2;
                float2 p0 = *(const float2*)(OS + r0 * 128 + d0);
                float2 p1 = *(const float2*)(OS + r1 * 128 + d0);
                *(float2*)(ob0 + d0) = make_float2((o_acc[fm][fn][0] + p0.x) * i0,
                                                   (o_acc[fm][fn][1] + p0.y) * i0);
                *(float2*)(ob1 + d0) = make_float2((o_acc[fm][fn][2] + p1.x) * i1,
                                                   (o_acc[fm][fn][3] + p1.y) * i1);
            }
        }
    }
}

// ---------------- scores normalization: fp16 raw -> fp32 normalized ----------------
__global__ void k_scale(float* __restrict__ scores){
    const size_t total8 = (size_t)BH_ * N_ * N_ / 8;   // units of 8 halves
    const size_t stride = (size_t)gridDim.x * blockDim.x;
    const uint4* src = (const uint4*)g_p16;
    for (size_t i = (size_t)blockIdx.x * blockDim.x + threadIdx.x; i < total8; i += stride){
        const size_t row = i >> 7;          // 128 8-elt units per 1024-col row
        const float invd = g_inv[row];
        uint4 hv = src[i];
        float2 f0 = __half22float2(*(const __half2*)&hv.x);
        float2 f1 = __half22float2(*(const __half2*)&hv.y);
        float2 f2 = __half22float2(*(const __half2*)&hv.z);
        float2 f3 = __half22float2(*(const __half2*)&hv.w);
        float4 o0 = make_float4(f0.x * invd, f0.y * invd, f1.x * invd, f1.y * invd);
        float4 o1 = make_float4(f2.x * invd, f2.y * invd, f3.x * invd, f3.y * invd);
        *(float4*)(scores + i * 8)     = o0;
        *(float4*)(scores + i * 8 + 4) = o1;
    }
}

extern "C" void kernel_launch(void* const* d_in, const int* in_sizes, int n_in,
                              void* d_out, int out_size)
{
    const float* q  = (const float*)d_in[0];
    const float* k  = (const float*)d_in[1];
    const float* v  = (const float*)d_in[2];
    const float* c  = (const float*)d_in[3];
    const float* dq = (const float*)d_in[4];
    const float* dk = (const float*)d_in[5];
    const float* ww = (const float*)d_in[6];
    const float* bw = (const float*)d_in[7];
    const float* wb = (const float*)d_in[8];
    const float* bb = (const float*)d_in[9];

    float* out    = (float*)d_out;
    float* scores = out + (size_t)BH_ * N_ * DH_;

    cudaFuncSetAttribute(k_main, cudaFuncAttributeMaxDynamicSharedMemorySize, SMEM_TOTAL);

    k_prep<<<784, 256>>>(q, k, v, dk);
    k_main<<<BH_ * 8, 256, SMEM_TOTAL>>>(c, dq, ww, bw, wb, bb, out);
    k_scale<<<8192, 256>>>(scores);
}